// round 6
// baseline (speedup 1.0000x reference)
#include <cuda_runtime.h>
#include <math.h>

namespace {
constexpr int B_ = 32, L_ = 32, D_ = 512, H_ = 512;
constexpr int H2_ = 1024, H5_ = 2560;
constexpr int PSLOT = 64, ZSLOT = 63;   // pool slots per batch; 63 = zero slot
constexpr int CSLOT = 96, DSLOT = 95;   // cache slots per batch; 95 = dummy
constexpr int NCTA = 80;                // persistent grid (all resident, = #N-tiles)
}

typedef unsigned long long u64;

__device__ __align__(16) float g_poolH[B_ * PSLOT * H_];
__device__ __align__(16) float g_poolC[B_ * PSLOT * H_];
__device__ __align__(16) float g_uL[B_ * PSLOT * H5_];
__device__ __align__(16) float g_uR[B_ * PSLOT * H5_];
__device__ __align__(16) float g_cacheH[B_ * CSLOT * H_];
__device__ __align__(16) float g_cacheC[B_ * CSLOT * H_];
__device__ float g_logit[B_ * CSLOT];
__device__ int4  g_tasks[2 * B_];
__device__ int   g_newSlot[B_];
__device__ int   g_slotOf[B_ * L_];
__device__ int   g_cidx[B_ * L_];
__device__ unsigned g_barCnt[64];

__device__ __forceinline__ float sigm(float x) { return 1.f / (1.f + expf(-x)); }

#define FFMA2(d, a, b) asm("fma.rn.f32x2 %0, %1, %2, %0;" : "+l"(d) : "l"(a), "l"(b))
__device__ __forceinline__ u64 pk2(float lo, float hi) {
    u64 r; asm("mov.b64 %0, {%1, %2};" : "=l"(r) : "f"(lo), "f"(hi)); return r;
}
__device__ __forceinline__ float2 up2(u64 p) {
    float2 r; asm("mov.b64 {%0, %1}, %2;" : "=f"(r.x), "=f"(r.y) : "l"(p)); return r;
}

__device__ __forceinline__ void gridBar(int id) {
    __syncthreads();
    if (threadIdx.x == 0) {
        __threadfence();
        atomicAdd(&g_barCnt[id], 1u);
        while (*(volatile unsigned*)&g_barCnt[id] < (unsigned)NCTA) {}
        __threadfence();
    }
    __syncthreads();
}

// ---------------------------------------------------------------------------
__global__ void kInit() {
    int t = blockIdx.x * blockDim.x + threadIdx.x;   // 4096 threads
    if (t < 64) g_barCnt[t] = 0u;
    if (t < B_ * L_) {
        int p = t % L_;
        g_slotOf[t] = p;
        g_cidx[t]   = (p < L_ - 1) ? p : DSLOT;
    }
    if (t < B_) g_logit[t * CSLOT + DSLOT] = 0.f;
    for (int i = t; i < B_ * H_; i += 4096) {
        int b = i / H_, j = i % H_;
        g_poolH[(b * PSLOT + ZSLOT) * H_ + j] = 0.f;
        g_poolC[(b * PSLOT + ZSLOT) * H_ + j] = 0.f;
        g_cacheH[(b * CSLOT + DSLOT) * H_ + j] = 0.f;
        g_cacheC[(b * CSLOT + DSLOT) * H_ + j] = 0.f;
    }
    for (int i = t; i < B_ * H5_; i += 4096) {
        int b = i / H5_, j = i % H5_;
        g_uL[(b * PSLOT + ZSLOT) * H5_ + j] = 0.f;
        g_uR[(b * PSLOT + ZSLOT) * H5_ + j] = 0.f;
    }
}

// ---------------------------------------------------------------------------
// 64x64 f32x2 GEMM core: diag/anti-diag packed accumulators.
// aRow = staging thread's A row base (row m0 + (tid>>2), k-contiguous).
// bPtr = &W[(tid>>4)*ldb + n0 + (tid&15)*4].
// ---------------------------------------------------------------------------
__device__ __forceinline__ void gemm64core(const float* aRow, const float* bPtr,
                                           int ldb, int K, int tid,
                                           float (*Xs)[68], float (*Ws)[68],
                                           u64* accd, u64* accx) {
    const int lq = tid & 3, lm = tid >> 2;
    const int wr = tid >> 4, wc = tid & 15;
    const int ty = tid >> 4, tx = tid & 15;
    float4 xr = *(const float4*)(aRow + lq * 4);
    float4 wv = *(const float4*)bPtr;
    for (int k0 = 0; k0 < K; k0 += 16) {
        Xs[lq*4+0][lm] = xr.x; Xs[lq*4+1][lm] = xr.y;
        Xs[lq*4+2][lm] = xr.z; Xs[lq*4+3][lm] = xr.w;
        *(float4*)&Ws[wr][wc*4] = wv;
        __syncthreads();
        if (k0 + 16 < K) {
            xr = *(const float4*)(aRow + k0 + 16 + lq * 4);
            wv = *(const float4*)(bPtr + (k0 + 16) * ldb);
        }
#pragma unroll
        for (int kk = 0; kk < 16; kk++) {
            u64 an0 = *(const u64*)&Xs[kk][ty*4];
            u64 an1 = *(const u64*)&Xs[kk][ty*4+2];
            float4 bv = *(const float4*)&Ws[kk][tx*4];
            u64 bn0 = pk2(bv.x, bv.y), bs0 = pk2(bv.y, bv.x);
            u64 bn1 = pk2(bv.z, bv.w), bs1 = pk2(bv.w, bv.z);
            FFMA2(accd[0], an0, bn0); FFMA2(accx[0], an0, bs0);
            FFMA2(accd[1], an0, bn1); FFMA2(accx[1], an0, bs1);
            FFMA2(accd[2], an1, bn0); FFMA2(accx[2], an1, bs0);
            FFMA2(accd[3], an1, bn1); FFMA2(accx[3], an1, bs1);
        }
        __syncthreads();
    }
}

// ---------------------------------------------------------------------------
// Leaf GEMM: hc = inp @ W_word + b_word. M=1024, N=1024, K=512.
// ---------------------------------------------------------------------------
__global__ void __launch_bounds__(256) kLeafGemm(const float* __restrict__ inp,
                                                 const float* __restrict__ Ww,
                                                 const float* __restrict__ bw,
                                                 float* __restrict__ nodes) {
    const int m0 = blockIdx.x * 64, n0 = blockIdx.y * 64;
    __shared__ __align__(16) float Xs[16][68];
    __shared__ __align__(16) float Ws[16][68];
    const int tid = threadIdx.x;
    u64 accd[4] = {0,0,0,0}, accx[4] = {0,0,0,0};
    const float* aRow = inp + (m0 + (tid >> 2)) * D_;
    const float* bPtr = Ww + (tid >> 4) * H2_ + n0 + (tid & 15) * 4;
    gemm64core(aRow, bPtr, H2_, D_, tid, Xs, Ws, accd, accx);

    const int ty = tid >> 4, tx = tid & 15;
    float4 bv = *(const float4*)(bw + n0 + tx * 4);
    float rowv[4][4];
#pragma unroll
    for (int rp = 0; rp < 2; rp++) {
        float2 d0 = up2(accd[rp*2]),   x0 = up2(accx[rp*2]);
        float2 d1 = up2(accd[rp*2+1]), x1 = up2(accx[rp*2+1]);
        rowv[rp*2][0]   = d0.x + bv.x; rowv[rp*2][1]   = x0.x + bv.y;
        rowv[rp*2][2]   = d1.x + bv.z; rowv[rp*2][3]   = x1.x + bv.w;
        rowv[rp*2+1][0] = x0.y + bv.x; rowv[rp*2+1][1] = d0.y + bv.y;
        rowv[rp*2+1][2] = x1.y + bv.z; rowv[rp*2+1][3] = d1.y + bv.w;
    }
#pragma unroll
    for (int e = 0; e < 4; e++) {
        int m = m0 + ty * 4 + e, b = m / L_, l = m % L_;
        int n = n0 + tx * 4;
        if (n0 < H_) {
            *(float4*)&g_poolH[(b * PSLOT + l) * H_ + n] =
                make_float4(rowv[e][0], rowv[e][1], rowv[e][2], rowv[e][3]);
            *(float4*)&nodes[(b * 63 + l) * H_ + n] =
                make_float4(rowv[e][0], rowv[e][1], rowv[e][2], rowv[e][3]);
        } else {
            *(float4*)&g_poolC[(b * PSLOT + l) * H_ + (n - H_)] =
                make_float4(rowv[e][0], rowv[e][1], rowv[e][2], rowv[e][3]);
        }
    }
}

// ---------------------------------------------------------------------------
// Front u-GEMM over ALL leaf slots (garbage leaves included — the reference's
// frozen-replay node reads them): M=1024, N=5120 (uL|uR), K=512.
// Grid MUST be dim3(16, 80): 80*64 = 5120 N-columns exactly.
// ---------------------------------------------------------------------------
__global__ void __launch_bounds__(256) kUGemm0(const float* __restrict__ Wc) {
    const int m0 = blockIdx.x * 64;
    const int n0 = blockIdx.y * 64;
    const int half = (n0 >= H5_) ? 1 : 0;
    const int nn = n0 - half * H5_;
    __shared__ __align__(16) float Xs[16][68];
    __shared__ __align__(16) float Ws[16][68];
    const int tid = threadIdx.x;
    u64 accd[4] = {0,0,0,0}, accx[4] = {0,0,0,0};
    int m = m0 + (tid >> 2);
    const float* aRow = g_poolH + (((m >> 5) * PSLOT) + (m & 31)) * H_;
    const float* bPtr = Wc + (half * H_ + (tid >> 4)) * H5_ + nn + (tid & 15) * 4;
    gemm64core(aRow, bPtr, H5_, H_, tid, Xs, Ws, accd, accx);

    const int ty = tid >> 4, tx = tid & 15;
    float* U = half ? g_uR : g_uL;
#pragma unroll
    for (int rp = 0; rp < 2; rp++) {
        float2 d0 = up2(accd[rp*2]),   x0 = up2(accx[rp*2]);
        float2 d1 = up2(accd[rp*2+1]), x1 = up2(accx[rp*2+1]);
        int r0 = m0 + ty * 4 + rp * 2;
        int b0 = r0 >> 5, s0 = r0 & 31;
        int b1 = (r0 + 1) >> 5, s1 = (r0 + 1) & 31;
        *(float4*)&U[(b0 * PSLOT + s0) * H5_ + nn + tx * 4] =
            make_float4(d0.x, x0.x, d1.x, x1.x);
        *(float4*)&U[(b1 * PSLOT + s1) * H5_ + nn + tx * 4] =
            make_float4(x0.y, d0.y, x1.y, d1.y);
    }
}

// ---------------------------------------------------------------------------
// Vectorized pair activation: lt in [0,128), each thread does 4 elements.
// ---------------------------------------------------------------------------
__device__ __forceinline__ void actPair4(int b, int ls, int rs, int cs,
                                         const float* __restrict__ bc,
                                         const float* __restrict__ q,
                                         int lt, float* red) {
    const float* ul = g_uL + (b * PSLOT + ls) * H5_;
    const float* ur = g_uR + (b * PSLOT + rs) * H5_;
    const float* cl = g_poolC + (b * PSLOT + ls) * H_;
    const float* cr = g_poolC + (b * PSLOT + rs) * H_;
    float* oh = g_cacheH + (b * CSLOT + cs) * H_;
    float* oc = g_cacheC + (b * CSLOT + cs) * H_;
    int j = lt * 4;
    float G[5][4];
#pragma unroll
    for (int g = 0; g < 5; g++) {
        float4 a = *(const float4*)(ul + g * H_ + j);
        float4 r = *(const float4*)(ur + g * H_ + j);
        float4 c = *(const float4*)(bc + g * H_ + j);
        G[g][0] = a.x + r.x + c.x; G[g][1] = a.y + r.y + c.y;
        G[g][2] = a.z + r.z + c.z; G[g][3] = a.w + r.w + c.w;
    }
    float4 cl4 = *(const float4*)(cl + j);
    float4 cr4 = *(const float4*)(cr + j);
    float4 q4  = *(const float4*)(q + j);
    float clv[4] = {cl4.x, cl4.y, cl4.z, cl4.w};
    float crv[4] = {cr4.x, cr4.y, cr4.z, cr4.w};
    float hv[4], cv[4];
#pragma unroll
    for (int l = 0; l < 4; l++) {
        float c = clv[l] * sigm(G[1][l] + 1.f) + crv[l] * sigm(G[2][l] + 1.f)
                + tanhf(G[3][l]) * sigm(G[0][l]);
        hv[l] = sigm(G[4][l]) * tanhf(c); cv[l] = c;
    }
    *(float4*)(oh + j) = make_float4(hv[0], hv[1], hv[2], hv[3]);
    *(float4*)(oc + j) = make_float4(cv[0], cv[1], cv[2], cv[3]);
    float acc = hv[0]*q4.x + hv[1]*q4.y + hv[2]*q4.z + hv[3]*q4.w;
    for (int o = 16; o > 0; o >>= 1) acc += __shfl_down_sync(0xffffffffu, acc, o);
    if ((lt & 31) == 0) red[lt >> 5] = acc;
    __syncthreads();
    if (lt == 0)
        g_logit[b * CSLOT + cs] = red[0] + red[1] + red[2] + red[3];
}

__global__ void __launch_bounds__(128) kAct0(const int* __restrict__ len,
                                             const float* __restrict__ bc,
                                             const float* __restrict__ q) {
    __shared__ float red[4];
    int b = blockIdx.y, j = blockIdx.x;
    if (j >= len[b] - 1) return;
    actPair4(b, j, j + 1, j, bc, q, threadIdx.x, red);
}

// ---------------------------------------------------------------------------
__device__ void doSelect(int b, int stepI, const int* __restrict__ len,
                         float* __restrict__ nodes, float* __restrict__ hf,
                         float* __restrict__ cf,
                         int* sPos, int* sPair, int* sKp) {
    int t = threadIdx.x;
    if (t < 32) sPos[t] = g_slotOf[b * L_ + t];
    if (t < 31) sPair[t] = g_cidx[b * L_ + t];
    __syncthreads();
    int lb = len[b];
    if (stepI < lb - 1) {
        if (t == 0) {
            int cand = lb - 1 - stepI, k = 0;
            float best = -1e30f;
            for (int j = 0; j < cand; j++) {
                float v = g_logit[b * CSLOT + sPair[j]];
                if (v > best) { best = v; k = j; }
            }
            *sKp = k;
        }
        __syncthreads();
        int k = *sKp, cs = sPair[k], mslot = 32 + stepI;
        const float* ch = &g_cacheH[(b * CSLOT + cs) * H_];
        const float* cc = &g_cacheC[(b * CSLOT + cs) * H_];
        float* ph = &g_poolH[(b * PSLOT + mslot) * H_];
        float* pc = &g_poolC[(b * PSLOT + mslot) * H_];
        float* nd = &nodes[(b * 63 + 32 + stepI) * H_];
        for (int j = t; j < H_; j += blockDim.x) {
            float hvv = ch[j], cvv = cc[j];
            ph[j] = hvv; pc[j] = cvv; nd[j] = hvv;
            if (stepI == L_ - 2) { hf[b * H_ + j] = hvv; cf[b * H_ + j] = cvv; }
        }
        if (t < 32) {
            int np = (t < k) ? sPos[t] : (t == k) ? mslot : (t < 31) ? sPos[t + 1] : ZSLOT;
            g_slotOf[b * L_ + t] = np;
        }
        if (t < 31) {
            int np;
            if      (t <  k - 1) np = sPair[t];
            else if (t == k - 1) np = 31 + 2 * stepI;
            else if (t == k)     np = 32 + 2 * stepI;
            else if (t < 30)     np = sPair[t + 1];
            else                 np = DSLOT;
            g_cidx[b * L_ + t] = np;
        }
        if (t == 0) {
            int A = 31 + 2 * stepI, Bc = 32 + 2 * stepI;
            g_tasks[2 * b] = (k > 0) ? make_int4(b, sPos[k - 1], mslot, A)
                                     : make_int4(b, ZSLOT, ZSLOT, DSLOT);
            int r = (k + 2 <= 31) ? sPos[k + 2] : ZSLOT;
            g_tasks[2 * b + 1] = make_int4(b, mslot, r, Bc);
            g_newSlot[b] = mslot;
        }
    } else {
        float* nd = &nodes[(b * 63 + 32 + stepI) * H_];
        if (stepI == L_ - 2) {
            int rs = sPos[0];
            const float* ph = &g_poolH[(b * PSLOT + rs) * H_];
            const float* pc = &g_poolC[(b * PSLOT + rs) * H_];
            for (int j = t; j < H_; j += blockDim.x) {
                float hvv = ph[j];
                nd[j] = hvv; hf[b * H_ + j] = hvv; cf[b * H_ + j] = pc[j];
            }
        } else {
            int cs = sPair[0];
            const float* ch = &g_cacheH[(b * CSLOT + cs) * H_];
            for (int j = t; j < H_; j += blockDim.x) nd[j] = ch[j];
        }
        if (t == 0) {
            g_tasks[2 * b]     = make_int4(b, ZSLOT, ZSLOT, DSLOT);
            g_tasks[2 * b + 1] = make_int4(b, ZSLOT, ZSLOT, DSLOT);
            g_newSlot[b] = ZSLOT;
        }
    }
    __syncthreads();
}

// ---------------------------------------------------------------------------
// Persistent: select_0, then 30x [u-GEMM (80 CTAs) | act+select (32 CTAs)].
// ---------------------------------------------------------------------------
__global__ void __launch_bounds__(256, 1) kPersist(const int* __restrict__ len,
                                                   const float* __restrict__ Wc,
                                                   const float* __restrict__ bc,
                                                   const float* __restrict__ q,
                                                   float* __restrict__ nodes,
                                                   float* __restrict__ hf,
                                                   float* __restrict__ cf) {
    const int cta = blockIdx.x, tid = threadIdx.x;
    __shared__ __align__(16) float As[16][36];
    __shared__ __align__(16) float Ws[16][68];
    __shared__ int sSlot[32];
    __shared__ int sPos[32], sPair[31], sK;
    __shared__ float red[8];

    if (cta < B_) doSelect(cta, 0, len, nodes, hf, cf, sPos, sPair, &sK);
    gridBar(0);

    const int n0g = cta * 64;
    const int half = (n0g >= H5_) ? 1 : 0;
    const int nn = n0g - half * H5_;
    const float* bPtr = Wc + (half * H_ + (tid >> 4)) * H5_ + nn + (tid & 15) * 4;
    const int mS = tid >> 2, qS = tid & 3;       // staging (tid<128)
    const int mg = tid >> 4, ng = tid & 15;      // compute

    for (int i = 1; i <= L_ - 2; i++) {
        // ---- phase 1: u-GEMM for new nodes: M=32, N=5120, K=512
        if (tid < B_) sSlot[tid] = ((volatile int*)g_newSlot)[tid];
        __syncthreads();
        {
            const float* aPtr = (tid < 128)
                ? g_poolH + (mS * PSLOT + sSlot[mS]) * H_ + qS * 4 : g_poolH;
            float4 xr, wv;
            if (tid < 128) xr = *(const float4*)aPtr;
            wv = *(const float4*)bPtr;
            u64 d0 = 0, x0 = 0, d1 = 0, x1 = 0;
            for (int k0 = 0; k0 < H_; k0 += 16) {
                if (tid < 128) {
                    As[qS*4+0][mS] = xr.x; As[qS*4+1][mS] = xr.y;
                    As[qS*4+2][mS] = xr.z; As[qS*4+3][mS] = xr.w;
                }
                *(float4*)&Ws[tid >> 4][(tid & 15) * 4] = wv;
                __syncthreads();
                if (k0 + 16 < H_) {
                    if (tid < 128) xr = *(const float4*)(aPtr + k0 + 16);
                    wv = *(const float4*)(bPtr + (k0 + 16) * H5_);
                }
#pragma unroll
                for (int kk = 0; kk < 16; kk++) {
                    u64 ap = *(const u64*)&As[kk][mg * 2];
                    float4 bv = *(const float4*)&Ws[kk][ng * 4];
                    u64 bn0 = pk2(bv.x, bv.y), bs0 = pk2(bv.y, bv.x);
                    u64 bn1 = pk2(bv.z, bv.w), bs1 = pk2(bv.w, bv.z);
                    FFMA2(d0, ap, bn0); FFMA2(x0, ap, bs0);
                    FFMA2(d1, ap, bn1); FFMA2(x1, ap, bs1);
                }
                __syncthreads();
            }
            float* U = half ? g_uR : g_uL;
            float2 fd0 = up2(d0), fx0 = up2(x0), fd1 = up2(d1), fx1 = up2(x1);
            int r0 = mg * 2;
            *(float4*)&U[(r0 * PSLOT + sSlot[r0]) * H5_ + nn + ng * 4] =
                make_float4(fd0.x, fx0.x, fd1.x, fx1.x);
            *(float4*)&U[((r0 + 1) * PSLOT + sSlot[r0 + 1]) * H5_ + nn + ng * 4] =
                make_float4(fx0.y, fd0.y, fx1.y, fd1.y);
        }
        gridBar(2 * i - 1);
        // ---- phase 2: activation (2 tasks in warp-halves) + select
        if (cta < B_) {
            int4 tk = (tid < 128) ? g_tasks[2 * cta] : g_tasks[2 * cta + 1];
            actPair4(cta, tk.y, tk.z, tk.w, bc, q, tid & 127, red + ((tid >> 7) << 2));
            __syncthreads();
            doSelect(cta, i, len, nodes, hf, cf, sPos, sPair, &sK);
        }
        gridBar(2 * i);
    }
}

// ---------------------------------------------------------------------------
extern "C" void kernel_launch(void* const* d_in, const int* in_sizes, int n_in,
                              void* d_out, int out_size) {
    const float* inp = (const float*)d_in[0];
    const int*   len = (const int*)  d_in[1];
    const float* Ww  = (const float*)d_in[2];
    const float* bw  = (const float*)d_in[3];
    const float* Wc  = (const float*)d_in[4];
    const float* bc  = (const float*)d_in[5];
    const float* q   = (const float*)d_in[6];
    float* out   = (float*)d_out;
    float* hf    = out;
    float* cf    = out + B_ * H_;
    float* nodes = out + 2 * B_ * H_;

    kInit<<<16, 256>>>();
    kLeafGemm<<<dim3(16, 16), 256>>>(inp, Ww, bw, nodes);
    kUGemm0<<<dim3(16, 80), 256>>>(Wc);
    kAct0<<<dim3(31, B_), 128>>>(len, bc, q);
    kPersist<<<NCTA, 256>>>(len, Wc, bc, q, nodes, hf, cf);
}

// round 7
// speedup vs baseline: 1.5220x; 1.5220x over previous
#include <cuda_runtime.h>
#include <math.h>

namespace {
constexpr int B_ = 32, L_ = 32, D_ = 512, H_ = 512;
constexpr int H2_ = 1024, H5_ = 2560;
constexpr int PSLOT = 64, ZSLOT = 63;   // pool slots per batch; 63 = zero slot
constexpr int CSLOT = 96, DSLOT = 95;   // cache slots per batch; 95 = dummy
}

typedef unsigned long long u64;

__device__ __align__(16) float g_poolH[B_ * PSLOT * H_];
__device__ __align__(16) float g_poolC[B_ * PSLOT * H_];
__device__ __align__(16) float g_uL[B_ * PSLOT * H5_];
__device__ __align__(16) float g_uR[B_ * PSLOT * H5_];
__device__ __align__(16) float g_cacheH[B_ * CSLOT * H_];
__device__ __align__(16) float g_cacheC[B_ * CSLOT * H_];
__device__ float g_logit[B_ * CSLOT];
__device__ int4  g_tasks[2 * B_];
__device__ int   g_newSlot[B_];
__device__ int   g_slotOf[B_ * L_];
__device__ int   g_cidx[B_ * L_];

__device__ __forceinline__ float sigm(float x) { return 1.f / (1.f + expf(-x)); }

#define FFMA2(d, a, b) asm("fma.rn.f32x2 %0, %1, %2, %0;" : "+l"(d) : "l"(a), "l"(b))
__device__ __forceinline__ u64 pk2(float lo, float hi) {
    u64 r; asm("mov.b64 %0, {%1, %2};" : "=l"(r) : "f"(lo), "f"(hi)); return r;
}
__device__ __forceinline__ float2 up2(u64 p) {
    float2 r; asm("mov.b64 {%0, %1}, %2;" : "=f"(r.x), "=f"(r.y) : "l"(p)); return r;
}

// ---------------------------------------------------------------------------
__global__ void kInit() {
    int t = blockIdx.x * blockDim.x + threadIdx.x;   // 4096 threads
    if (t < B_ * L_) {
        int p = t % L_;
        g_slotOf[t] = p;
        g_cidx[t]   = (p < L_ - 1) ? p : DSLOT;
    }
    if (t < B_) g_logit[t * CSLOT + DSLOT] = 0.f;
    for (int i = t; i < B_ * H_; i += 4096) {
        int b = i / H_, j = i % H_;
        g_poolH[(b * PSLOT + ZSLOT) * H_ + j] = 0.f;
        g_poolC[(b * PSLOT + ZSLOT) * H_ + j] = 0.f;
        g_cacheH[(b * CSLOT + DSLOT) * H_ + j] = 0.f;
        g_cacheC[(b * CSLOT + DSLOT) * H_ + j] = 0.f;
    }
    for (int i = t; i < B_ * H5_; i += 4096) {
        int b = i / H5_, j = i % H5_;
        g_uL[(b * PSLOT + ZSLOT) * H5_ + j] = 0.f;
        g_uR[(b * PSLOT + ZSLOT) * H5_ + j] = 0.f;
    }
}

// ---------------------------------------------------------------------------
// 64x64 f32x2 GEMM core, adjacent-N packed accumulators:
//   acc[m][0] = (out[n0],out[n1]), acc[m][1] = (out[n2],out[n3]).
// Per-element accumulation order identical to scalar version.
// ---------------------------------------------------------------------------
__device__ __forceinline__ void gemm64core(const float* aRow, const float* bPtr,
                                           int ldb, int K, int tid,
                                           float (*Xs)[68], float (*Ws)[68],
                                           u64 (*acc)[2]) {
    const int lq = tid & 3, lm = tid >> 2;
    const int wr = tid >> 4, wc = tid & 15;
    const int ty = tid >> 4, tx = tid & 15;
    float4 xr = *(const float4*)(aRow + lq * 4);
    float4 wv = *(const float4*)bPtr;
    for (int k0 = 0; k0 < K; k0 += 16) {
        Xs[lq*4+0][lm] = xr.x; Xs[lq*4+1][lm] = xr.y;
        Xs[lq*4+2][lm] = xr.z; Xs[lq*4+3][lm] = xr.w;
        *(float4*)&Ws[wr][wc*4] = wv;
        __syncthreads();
        if (k0 + 16 < K) {
            xr = *(const float4*)(aRow + k0 + 16 + lq * 4);
            wv = *(const float4*)(bPtr + (k0 + 16) * ldb);
        }
#pragma unroll
        for (int kk = 0; kk < 16; kk++) {
            float4 a = *(const float4*)&Xs[kk][ty*4];
            u64 b01 = *(const u64*)&Ws[kk][tx*4];
            u64 b23 = *(const u64*)&Ws[kk][tx*4+2];
            u64 pa0 = pk2(a.x, a.x), pa1 = pk2(a.y, a.y);
            u64 pa2 = pk2(a.z, a.z), pa3 = pk2(a.w, a.w);
            FFMA2(acc[0][0], pa0, b01); FFMA2(acc[0][1], pa0, b23);
            FFMA2(acc[1][0], pa1, b01); FFMA2(acc[1][1], pa1, b23);
            FFMA2(acc[2][0], pa2, b01); FFMA2(acc[2][1], pa2, b23);
            FFMA2(acc[3][0], pa3, b01); FFMA2(acc[3][1], pa3, b23);
        }
        __syncthreads();
    }
}

// ---------------------------------------------------------------------------
// Leaf GEMM: hc = inp @ W_word + b_word. M=1024, N=1024, K=512.
// ---------------------------------------------------------------------------
__global__ void __launch_bounds__(256) kLeafGemm(const float* __restrict__ inp,
                                                 const float* __restrict__ Ww,
                                                 const float* __restrict__ bw,
                                                 float* __restrict__ nodes) {
    const int m0 = blockIdx.x * 64, n0 = blockIdx.y * 64;
    __shared__ __align__(16) float Xs[16][68];
    __shared__ __align__(16) float Ws[16][68];
    const int tid = threadIdx.x;
    u64 acc[4][2] = {};
    const float* aRow = inp + (m0 + (tid >> 2)) * D_;
    const float* bPtr = Ww + (tid >> 4) * H2_ + n0 + (tid & 15) * 4;
    gemm64core(aRow, bPtr, H2_, D_, tid, Xs, Ws, acc);

    const int ty = tid >> 4, tx = tid & 15;
    float4 bv = *(const float4*)(bw + n0 + tx * 4);
#pragma unroll
    for (int e = 0; e < 4; e++) {
        int m = m0 + ty * 4 + e, b = m / L_, l = m % L_;
        int n = n0 + tx * 4;
        float2 p0 = up2(acc[e][0]), p1 = up2(acc[e][1]);
        float4 v = make_float4(p0.x + bv.x, p0.y + bv.y, p1.x + bv.z, p1.y + bv.w);
        if (n0 < H_) {
            *(float4*)&g_poolH[(b * PSLOT + l) * H_ + n] = v;
            *(float4*)&nodes[(b * 63 + l) * H_ + n] = v;
        } else {
            *(float4*)&g_poolC[(b * PSLOT + l) * H_ + (n - H_)] = v;
        }
    }
}

// ---------------------------------------------------------------------------
// Front u-GEMM over ALL leaf slots (garbage leaves included — the reference's
// frozen-replay node reads them): M=1024, N=5120 (uL|uR), K=512.
// Grid MUST be dim3(16, 80).
// ---------------------------------------------------------------------------
__global__ void __launch_bounds__(256) kUGemm0(const float* __restrict__ Wc) {
    const int m0 = blockIdx.x * 64;
    const int n0 = blockIdx.y * 64;
    const int half = (n0 >= H5_) ? 1 : 0;
    const int nn = n0 - half * H5_;
    __shared__ __align__(16) float Xs[16][68];
    __shared__ __align__(16) float Ws[16][68];
    const int tid = threadIdx.x;
    u64 acc[4][2] = {};
    int m = m0 + (tid >> 2);
    const float* aRow = g_poolH + (((m >> 5) * PSLOT) + (m & 31)) * H_;
    const float* bPtr = Wc + (half * H_ + (tid >> 4)) * H5_ + nn + (tid & 15) * 4;
    gemm64core(aRow, bPtr, H5_, H_, tid, Xs, Ws, acc);

    const int ty = tid >> 4, tx = tid & 15;
    float* U = half ? g_uR : g_uL;
#pragma unroll
    for (int e = 0; e < 4; e++) {
        int r = m0 + ty * 4 + e;
        int b = r >> 5, s = r & 31;
        float2 p0 = up2(acc[e][0]), p1 = up2(acc[e][1]);
        *(float4*)&U[(b * PSLOT + s) * H5_ + nn + tx * 4] =
            make_float4(p0.x, p0.y, p1.x, p1.y);
    }
}

// ---------------------------------------------------------------------------
// Per-step u-GEMM: M=32 (one new node per batch), N=5120, K=512 split in 2.
// grid (80, 2): x = 64-col N tile, y = 256-wide K chunk. Results accumulate
// into U via fp32 atomicAdd — exactly 2 contributions per element onto a
// zeroed slot, so the sum is order-independent (deterministic).
// ---------------------------------------------------------------------------
__global__ void __launch_bounds__(256) kUGemmStep(const float* __restrict__ Wc) {
    const int n0g = blockIdx.x * 64;
    const int half = (n0g >= H5_) ? 1 : 0;
    const int nn = n0g - half * H5_;
    const int kb = blockIdx.y * 256;
    __shared__ __align__(16) float As[16][36];
    __shared__ __align__(16) float Ws[16][68];
    __shared__ int sSlot[32];
    const int tid = threadIdx.x;
    if (tid < B_) sSlot[tid] = g_newSlot[tid];
    __syncthreads();

    const int mS = tid >> 2, qS = tid & 3;       // A staging (tid<128): rows 0..31
    const int mg = tid >> 4, ng = tid & 15;      // compute: 2 rows, 4 cols
    const float* aPtr = (tid < 128)
        ? g_poolH + (mS * PSLOT + sSlot[mS]) * H_ + kb + qS * 4 : g_poolH;
    const float* bPtr = Wc + (half * H_ + kb + (tid >> 4)) * H5_ + nn + (tid & 15) * 4;

    float4 xr, wv;
    if (tid < 128) xr = *(const float4*)aPtr;
    wv = *(const float4*)bPtr;
    u64 acc[2][2] = {};
    for (int k0 = 0; k0 < 256; k0 += 16) {
        if (tid < 128) {
            As[qS*4+0][mS] = xr.x; As[qS*4+1][mS] = xr.y;
            As[qS*4+2][mS] = xr.z; As[qS*4+3][mS] = xr.w;
        }
        *(float4*)&Ws[tid >> 4][(tid & 15) * 4] = wv;
        __syncthreads();
        if (k0 + 16 < 256) {
            if (tid < 128) xr = *(const float4*)(aPtr + k0 + 16);
            wv = *(const float4*)(bPtr + (k0 + 16) * H5_);
        }
#pragma unroll
        for (int kk = 0; kk < 16; kk++) {
            float a0 = As[kk][mg * 2], a1 = As[kk][mg * 2 + 1];
            u64 b01 = *(const u64*)&Ws[kk][ng*4];
            u64 b23 = *(const u64*)&Ws[kk][ng*4+2];
            u64 pa0 = pk2(a0, a0), pa1 = pk2(a1, a1);
            FFMA2(acc[0][0], pa0, b01); FFMA2(acc[0][1], pa0, b23);
            FFMA2(acc[1][0], pa1, b01); FFMA2(acc[1][1], pa1, b23);
        }
        __syncthreads();
    }
    float* U = half ? g_uR : g_uL;
#pragma unroll
    for (int e = 0; e < 2; e++) {
        int r = mg * 2 + e;
        float* dst = U + (r * PSLOT + sSlot[r]) * H5_ + nn + ng * 4;
        float2 p0 = up2(acc[e][0]), p1 = up2(acc[e][1]);
        atomicAdd(dst + 0, p0.x); atomicAdd(dst + 1, p0.y);
        atomicAdd(dst + 2, p1.x); atomicAdd(dst + 3, p1.y);
    }
}

// ---------------------------------------------------------------------------
// Vectorized pair activation: lt in [0,128), each thread does 4 elements.
// ---------------------------------------------------------------------------
__device__ __forceinline__ void actPair4(int b, int ls, int rs, int cs,
                                         const float* __restrict__ bc,
                                         const float* __restrict__ q,
                                         int lt, float* red) {
    const float* ul = g_uL + (b * PSLOT + ls) * H5_;
    const float* ur = g_uR + (b * PSLOT + rs) * H5_;
    const float* cl = g_poolC + (b * PSLOT + ls) * H_;
    const float* cr = g_poolC + (b * PSLOT + rs) * H_;
    float* oh = g_cacheH + (b * CSLOT + cs) * H_;
    float* oc = g_cacheC + (b * CSLOT + cs) * H_;
    int j = lt * 4;
    float G[5][4];
#pragma unroll
    for (int g = 0; g < 5; g++) {
        float4 a = *(const float4*)(ul + g * H_ + j);
        float4 r = *(const float4*)(ur + g * H_ + j);
        float4 c = *(const float4*)(bc + g * H_ + j);
        G[g][0] = a.x + r.x + c.x; G[g][1] = a.y + r.y + c.y;
        G[g][2] = a.z + r.z + c.z; G[g][3] = a.w + r.w + c.w;
    }
    float4 cl4 = *(const float4*)(cl + j);
    float4 cr4 = *(const float4*)(cr + j);
    float4 q4  = *(const float4*)(q + j);
    float clv[4] = {cl4.x, cl4.y, cl4.z, cl4.w};
    float crv[4] = {cr4.x, cr4.y, cr4.z, cr4.w};
    float hv[4], cv[4];
#pragma unroll
    for (int l = 0; l < 4; l++) {
        float c = clv[l] * sigm(G[1][l] + 1.f) + crv[l] * sigm(G[2][l] + 1.f)
                + tanhf(G[3][l]) * sigm(G[0][l]);
        hv[l] = sigm(G[4][l]) * tanhf(c); cv[l] = c;
    }
    *(float4*)(oh + j) = make_float4(hv[0], hv[1], hv[2], hv[3]);
    *(float4*)(oc + j) = make_float4(cv[0], cv[1], cv[2], cv[3]);
    float acc = hv[0]*q4.x + hv[1]*q4.y + hv[2]*q4.z + hv[3]*q4.w;
    for (int o = 16; o > 0; o >>= 1) acc += __shfl_down_sync(0xffffffffu, acc, o);
    if ((lt & 31) == 0) red[lt >> 5] = acc;
    __syncthreads();
    if (lt == 0)
        g_logit[b * CSLOT + cs] = red[0] + red[1] + red[2] + red[3];
}

__global__ void __launch_bounds__(128) kAct0(const int* __restrict__ len,
                                             const float* __restrict__ bc,
                                             const float* __restrict__ q) {
    __shared__ float red[4];
    int b = blockIdx.y, j = blockIdx.x;
    if (j >= len[b] - 1) return;
    actPair4(b, j, j + 1, j, bc, q, threadIdx.x, red);
}

// ---------------------------------------------------------------------------
// Select for batch b at step stepI. Also zeroes the merge slot's u entries so
// the next step's K-split GEMM can accumulate atomically.
// ---------------------------------------------------------------------------
__device__ void doSelect(int b, int stepI, const int* __restrict__ len,
                         float* __restrict__ nodes, float* __restrict__ hf,
                         float* __restrict__ cf,
                         int* sPos, int* sPair, int* sKp) {
    int t = threadIdx.x;
    if (t < 32) sPos[t] = g_slotOf[b * L_ + t];
    if (t < 31) sPair[t] = g_cidx[b * L_ + t];
    __syncthreads();
    int lb = len[b];
    if (stepI < lb - 1) {
        if (t == 0) {
            int cand = lb - 1 - stepI, k = 0;
            float best = -1e30f;
            for (int j = 0; j < cand; j++) {
                float v = g_logit[b * CSLOT + sPair[j]];
                if (v > best) { best = v; k = j; }
            }
            *sKp = k;
        }
        __syncthreads();
        int k = *sKp, cs = sPair[k], mslot = 32 + stepI;
        const float* ch = &g_cacheH[(b * CSLOT + cs) * H_];
        const float* cc = &g_cacheC[(b * CSLOT + cs) * H_];
        float* ph = &g_poolH[(b * PSLOT + mslot) * H_];
        float* pc = &g_poolC[(b * PSLOT + mslot) * H_];
        float* nd = &nodes[(b * 63 + 32 + stepI) * H_];
        for (int j = t; j < H_; j += blockDim.x) {
            float hvv = ch[j], cvv = cc[j];
            ph[j] = hvv; pc[j] = cvv; nd[j] = hvv;
            if (stepI == L_ - 2) { hf[b * H_ + j] = hvv; cf[b * H_ + j] = cvv; }
        }
        // zero u slots for the atomic accumulation next step
        {
            float4 z = make_float4(0.f, 0.f, 0.f, 0.f);
            float* zl = g_uL + (b * PSLOT + mslot) * H5_;
            float* zr = g_uR + (b * PSLOT + mslot) * H5_;
            for (int j = t * 4; j < H5_; j += blockDim.x * 4) {
                *(float4*)(zl + j) = z;
                *(float4*)(zr + j) = z;
            }
        }
        if (t < 32) {
            int np = (t < k) ? sPos[t] : (t == k) ? mslot : (t < 31) ? sPos[t + 1] : ZSLOT;
            g_slotOf[b * L_ + t] = np;
        }
        if (t < 31) {
            int np;
            if      (t <  k - 1) np = sPair[t];
            else if (t == k - 1) np = 31 + 2 * stepI;
            else if (t == k)     np = 32 + 2 * stepI;
            else if (t < 30)     np = sPair[t + 1];
            else                 np = DSLOT;
            g_cidx[b * L_ + t] = np;
        }
        if (t == 0) {
            int A = 31 + 2 * stepI, Bc = 32 + 2 * stepI;
            g_tasks[2 * b] = (k > 0) ? make_int4(b, sPos[k - 1], mslot, A)
                                     : make_int4(b, ZSLOT, ZSLOT, DSLOT);
            int r = (k + 2 <= 31) ? sPos[k + 2] : ZSLOT;
            g_tasks[2 * b + 1] = make_int4(b, mslot, r, Bc);
            g_newSlot[b] = mslot;
        }
    } else {
        float* nd = &nodes[(b * 63 + 32 + stepI) * H_];
        if (stepI == L_ - 2) {
            int rs = sPos[0];
            const float* ph = &g_poolH[(b * PSLOT + rs) * H_];
            const float* pc = &g_poolC[(b * PSLOT + rs) * H_];
            for (int j = t; j < H_; j += blockDim.x) {
                float hvv = ph[j];
                nd[j] = hvv; hf[b * H_ + j] = hvv; cf[b * H_ + j] = pc[j];
            }
        } else {
            int cs = sPair[0];
            const float* ch = &g_cacheH[(b * CSLOT + cs) * H_];
            for (int j = t; j < H_; j += blockDim.x) nd[j] = ch[j];
        }
        if (t == 0) {
            g_tasks[2 * b]     = make_int4(b, ZSLOT, ZSLOT, DSLOT);
            g_tasks[2 * b + 1] = make_int4(b, ZSLOT, ZSLOT, DSLOT);
            g_newSlot[b] = ZSLOT;
        }
    }
    __syncthreads();
}

// ---------------------------------------------------------------------------
// Fused activation (2 tasks in warp-halves) + select. One CTA per batch.
// ---------------------------------------------------------------------------
__global__ void __launch_bounds__(256) kActSel(const int* __restrict__ len,
                                               const float* __restrict__ bc,
                                               const float* __restrict__ q,
                                               float* __restrict__ nodes,
                                               float* __restrict__ hf,
                                               float* __restrict__ cf,
                                               int stepI, int doAct) {
    __shared__ int sPos[32], sPair[31], sK;
    __shared__ float red[8];
    int b = blockIdx.x, tid = threadIdx.x;
    if (doAct) {
        int4 tk = (tid < 128) ? g_tasks[2 * b] : g_tasks[2 * b + 1];
        actPair4(b, tk.y, tk.z, tk.w, bc, q, tid & 127, red + ((tid >> 7) << 2));
        __syncthreads();
    }
    doSelect(b, stepI, len, nodes, hf, cf, sPos, sPair, &sK);
}

// ---------------------------------------------------------------------------
extern "C" void kernel_launch(void* const* d_in, const int* in_sizes, int n_in,
                              void* d_out, int out_size) {
    const float* inp = (const float*)d_in[0];
    const int*   len = (const int*)  d_in[1];
    const float* Ww  = (const float*)d_in[2];
    const float* bw  = (const float*)d_in[3];
    const float* Wc  = (const float*)d_in[4];
    const float* bc  = (const float*)d_in[5];
    const float* q   = (const float*)d_in[6];
    float* out   = (float*)d_out;
    float* hf    = out;
    float* cf    = out + B_ * H_;
    float* nodes = out + 2 * B_ * H_;

    kInit<<<16, 256>>>();
    kLeafGemm<<<dim3(16, 16), 256>>>(inp, Ww, bw, nodes);
    kUGemm0<<<dim3(16, 80), 256>>>(Wc);
    kAct0<<<dim3(31, B_), 128>>>(len, bc, q);
    kActSel<<<B_, 256>>>(len, bc, q, nodes, hf, cf, 0, 0);
    for (int i = 1; i <= L_ - 2; i++) {
        kUGemmStep<<<dim3(80, 2), 256>>>(Wc);
        kActSel<<<B_, 256>>>(len, bc, q, nodes, hf, cf, i, 1);
    }
}

// round 8
// speedup vs baseline: 1.5933x; 1.0468x over previous
#include <cuda_runtime.h>
#include <math.h>

namespace {
constexpr int B_ = 32, L_ = 32, D_ = 512, H_ = 512;
constexpr int H2_ = 1024, H5_ = 2560;
constexpr int PSLOT = 64, ZSLOT = 63;   // pool slots per batch; 63 = zero slot
constexpr int CSLOT = 96, DSLOT = 95;   // cache slots per batch; 95 = dummy
constexpr int NCTA = 160;               // fused step kernel grid (80 x 2)
}

typedef unsigned long long u64;

__device__ __align__(16) float g_poolH[B_ * PSLOT * H_];
__device__ __align__(16) float g_poolC[B_ * PSLOT * H_];
__device__ __align__(16) float g_uL[B_ * PSLOT * H5_];
__device__ __align__(16) float g_uR[B_ * PSLOT * H5_];
__device__ __align__(16) float g_cacheH[B_ * CSLOT * H_];
__device__ __align__(16) float g_cacheC[B_ * CSLOT * H_];
__device__ float g_logit[B_ * CSLOT];
__device__ int4  g_tasks[2 * B_];
__device__ int   g_newSlot[B_];
__device__ int   g_slotOf[B_ * L_];
__device__ int   g_cidx[B_ * L_];
__device__ unsigned g_barCnt[64];

__device__ __forceinline__ float sigm(float x) { return 1.f / (1.f + expf(-x)); }

#define FFMA2(d, a, b) asm("fma.rn.f32x2 %0, %1, %2, %0;" : "+l"(d) : "l"(a), "l"(b))
__device__ __forceinline__ u64 pk2(float lo, float hi) {
    u64 r; asm("mov.b64 %0, {%1, %2};" : "=l"(r) : "f"(lo), "f"(hi)); return r;
}
__device__ __forceinline__ float2 up2(u64 p) {
    float2 r; asm("mov.b64 {%0, %1}, %2;" : "=f"(r.x), "=f"(r.y) : "l"(p)); return r;
}

__device__ __forceinline__ void gridBar(int id) {
    __syncthreads();
    if (threadIdx.x == 0) {
        __threadfence();
        atomicAdd(&g_barCnt[id], 1u);
        while (*(volatile unsigned*)&g_barCnt[id] < (unsigned)NCTA) {}
        __threadfence();
    }
    __syncthreads();
}

// ---------------------------------------------------------------------------
__global__ void kInit() {
    int t = blockIdx.x * blockDim.x + threadIdx.x;   // 4096 threads
    if (t < 64) g_barCnt[t] = 0u;
    if (t < B_ * L_) {
        int p = t % L_;
        g_slotOf[t] = p;
        g_cidx[t]   = (p < L_ - 1) ? p : DSLOT;
    }
    if (t < B_) g_logit[t * CSLOT + DSLOT] = 0.f;
    for (int i = t; i < B_ * H_; i += 4096) {
        int b = i / H_, j = i % H_;
        g_poolH[(b * PSLOT + ZSLOT) * H_ + j] = 0.f;
        g_poolC[(b * PSLOT + ZSLOT) * H_ + j] = 0.f;
        g_cacheH[(b * CSLOT + DSLOT) * H_ + j] = 0.f;
        g_cacheC[(b * CSLOT + DSLOT) * H_ + j] = 0.f;
    }
    for (int i = t; i < B_ * H5_; i += 4096) {
        int b = i / H5_, j = i % H5_;
        g_uL[(b * PSLOT + ZSLOT) * H5_ + j] = 0.f;
        g_uR[(b * PSLOT + ZSLOT) * H5_ + j] = 0.f;
    }
}

// ---------------------------------------------------------------------------
// 64x128 GEMM core, 128 threads, 8 rows x 8 cols per thread (f32x2 packed,
// adjacent-N pairs at cols {32p + tx*2, 32p + tx*2 + 1}, conflict-free LDS).
// aPtr = A row (m0 + tid/2) base + (tid&1)*8.  bPtr = W + (tid>>3)*ldb + n0 + (tid&7)*4.
// ---------------------------------------------------------------------------
__device__ __forceinline__ void gemm128core(const float* aPtr, const float* bPtr,
                                            int ldb, int K, int tid,
                                            float (*Xs)[68], float (*Ws)[132],
                                            u64 (*acc)[4]) {
    const int lm = tid >> 1, koff = (tid & 1) * 8;
    const int wr = tid >> 3, wj = tid & 7;
    const int ty = tid >> 4, tx = tid & 15;
    float4 xa0 = *(const float4*)(aPtr);
    float4 xa1 = *(const float4*)(aPtr + 4);
    float4 wv0 = *(const float4*)(bPtr);
    float4 wv1 = *(const float4*)(bPtr + 32);
    float4 wv2 = *(const float4*)(bPtr + 64);
    float4 wv3 = *(const float4*)(bPtr + 96);
    for (int k0 = 0; k0 < K; k0 += 16) {
        Xs[koff+0][lm]=xa0.x; Xs[koff+1][lm]=xa0.y; Xs[koff+2][lm]=xa0.z; Xs[koff+3][lm]=xa0.w;
        Xs[koff+4][lm]=xa1.x; Xs[koff+5][lm]=xa1.y; Xs[koff+6][lm]=xa1.z; Xs[koff+7][lm]=xa1.w;
        *(float4*)&Ws[wr][wj*4     ] = wv0;
        *(float4*)&Ws[wr][wj*4 + 32] = wv1;
        *(float4*)&Ws[wr][wj*4 + 64] = wv2;
        *(float4*)&Ws[wr][wj*4 + 96] = wv3;
        __syncthreads();
        if (k0 + 16 < K) {
            xa0 = *(const float4*)(aPtr + k0 + 16);
            xa1 = *(const float4*)(aPtr + k0 + 20);
            const float* bn = bPtr + (k0 + 16) * ldb;
            wv0 = *(const float4*)(bn);
            wv1 = *(const float4*)(bn + 32);
            wv2 = *(const float4*)(bn + 64);
            wv3 = *(const float4*)(bn + 96);
        }
#pragma unroll
        for (int kk = 0; kk < 16; kk++) {
            u64 bb[4];
            bb[0] = *(const u64*)&Ws[kk][tx*2];
            bb[1] = *(const u64*)&Ws[kk][32 + tx*2];
            bb[2] = *(const u64*)&Ws[kk][64 + tx*2];
            bb[3] = *(const u64*)&Ws[kk][96 + tx*2];
            float4 a0 = *(const float4*)&Xs[kk][ty*8];
            float4 a1 = *(const float4*)&Xs[kk][ty*8+4];
            u64 pa[8];
            pa[0]=pk2(a0.x,a0.x); pa[1]=pk2(a0.y,a0.y); pa[2]=pk2(a0.z,a0.z); pa[3]=pk2(a0.w,a0.w);
            pa[4]=pk2(a1.x,a1.x); pa[5]=pk2(a1.y,a1.y); pa[6]=pk2(a1.z,a1.z); pa[7]=pk2(a1.w,a1.w);
#pragma unroll
            for (int r = 0; r < 8; r++)
#pragma unroll
                for (int p = 0; p < 4; p++)
                    FFMA2(acc[r][p], pa[r], bb[p]);
        }
        __syncthreads();
    }
}

// ---------------------------------------------------------------------------
// Leaf GEMM: hc = inp @ W_word + b_word. M=1024, N=1024, K=512. grid(16,8),128thr.
// ---------------------------------------------------------------------------
__global__ void __launch_bounds__(128) kLeafGemm(const float* __restrict__ inp,
                                                 const float* __restrict__ Ww,
                                                 const float* __restrict__ bw,
                                                 float* __restrict__ nodes) {
    const int m0 = blockIdx.x * 64, n0 = blockIdx.y * 128;
    __shared__ __align__(16) float Xs[16][68];
    __shared__ __align__(16) float Ws[16][132];
    const int tid = threadIdx.x;
    u64 acc[8][4] = {};
    const float* aPtr = inp + (m0 + (tid >> 1)) * D_ + (tid & 1) * 8;
    const float* bPtr = Ww + (tid >> 3) * H2_ + n0 + (tid & 7) * 4;
    gemm128core(aPtr, bPtr, H2_, D_, tid, Xs, Ws, acc);

    const int ty = tid >> 4, tx = tid & 15;
    const int cHalf = (n0 >= H_) ? 1 : 0;
#pragma unroll
    for (int r = 0; r < 8; r++) {
        int m = m0 + ty * 8 + r, b = m / L_, l = m % L_;
#pragma unroll
        for (int p = 0; p < 4; p++) {
            int n = n0 + 32 * p + tx * 2;
            float2 bias = *(const float2*)(bw + n);
            float2 v = up2(acc[r][p]);
            v.x += bias.x; v.y += bias.y;
            if (!cHalf) {
                *(float2*)&g_poolH[(b * PSLOT + l) * H_ + n] = v;
                *(float2*)&nodes[(b * 63 + l) * H_ + n] = v;
            } else {
                *(float2*)&g_poolC[(b * PSLOT + l) * H_ + (n - H_)] = v;
            }
        }
    }
}

// ---------------------------------------------------------------------------
// Front u-GEMM over ALL leaf slots: M=1024, N=5120 (uL|uR), K=512. grid(16,40).
// ---------------------------------------------------------------------------
__global__ void __launch_bounds__(128) kUGemm0(const float* __restrict__ Wc) {
    const int m0 = blockIdx.x * 64;
    const int n0 = blockIdx.y * 128;
    const int half = (n0 >= H5_) ? 1 : 0;
    const int nn = n0 - half * H5_;
    __shared__ __align__(16) float Xs[16][68];
    __shared__ __align__(16) float Ws[16][132];
    const int tid = threadIdx.x;
    u64 acc[8][4] = {};
    int mrow = m0 + (tid >> 1);
    const float* aPtr = g_poolH + (((mrow >> 5) * PSLOT) + (mrow & 31)) * H_ + (tid & 1) * 8;
    const float* bPtr = Wc + (half * H_ + (tid >> 3)) * H5_ + nn + (tid & 7) * 4;
    gemm128core(aPtr, bPtr, H5_, H_, tid, Xs, Ws, acc);

    const int ty = tid >> 4, tx = tid & 15;
    float* U = half ? g_uR : g_uL;
#pragma unroll
    for (int r = 0; r < 8; r++) {
        int row = m0 + ty * 8 + r;
        int b = row >> 5, s = row & 31;
        float* dst = U + (b * PSLOT + s) * H5_ + nn;
#pragma unroll
        for (int p = 0; p < 4; p++)
            *(float2*)&dst[32 * p + tx * 2] = up2(acc[r][p]);
    }
}

// ---------------------------------------------------------------------------
// Vectorized pair activation: lt in [0,128), each thread does 4 elements.
// ---------------------------------------------------------------------------
__device__ __forceinline__ void actPair4(int b, int ls, int rs, int cs,
                                         const float* __restrict__ bc,
                                         const float* __restrict__ q,
                                         int lt, float* red) {
    const float* ul = g_uL + (b * PSLOT + ls) * H5_;
    const float* ur = g_uR + (b * PSLOT + rs) * H5_;
    const float* cl = g_poolC + (b * PSLOT + ls) * H_;
    const float* cr = g_poolC + (b * PSLOT + rs) * H_;
    float* oh = g_cacheH + (b * CSLOT + cs) * H_;
    float* oc = g_cacheC + (b * CSLOT + cs) * H_;
    int j = lt * 4;
    float G[5][4];
#pragma unroll
    for (int g = 0; g < 5; g++) {
        float4 a = *(const float4*)(ul + g * H_ + j);
        float4 r = *(const float4*)(ur + g * H_ + j);
        float4 c = *(const float4*)(bc + g * H_ + j);
        G[g][0] = a.x + r.x + c.x; G[g][1] = a.y + r.y + c.y;
        G[g][2] = a.z + r.z + c.z; G[g][3] = a.w + r.w + c.w;
    }
    float4 cl4 = *(const float4*)(cl + j);
    float4 cr4 = *(const float4*)(cr + j);
    float4 q4  = *(const float4*)(q + j);
    float clv[4] = {cl4.x, cl4.y, cl4.z, cl4.w};
    float crv[4] = {cr4.x, cr4.y, cr4.z, cr4.w};
    float hv[4], cv[4];
#pragma unroll
    for (int l = 0; l < 4; l++) {
        float c = clv[l] * sigm(G[1][l] + 1.f) + crv[l] * sigm(G[2][l] + 1.f)
                + tanhf(G[3][l]) * sigm(G[0][l]);
        hv[l] = sigm(G[4][l]) * tanhf(c); cv[l] = c;
    }
    *(float4*)(oh + j) = make_float4(hv[0], hv[1], hv[2], hv[3]);
    *(float4*)(oc + j) = make_float4(cv[0], cv[1], cv[2], cv[3]);
    float acc = hv[0]*q4.x + hv[1]*q4.y + hv[2]*q4.z + hv[3]*q4.w;
    for (int o = 16; o > 0; o >>= 1) acc += __shfl_down_sync(0xffffffffu, acc, o);
    if ((lt & 31) == 0) red[lt >> 5] = acc;
    __syncthreads();
    if (lt == 0)
        g_logit[b * CSLOT + cs] = red[0] + red[1] + red[2] + red[3];
}

__global__ void __launch_bounds__(128) kAct0(const int* __restrict__ len,
                                             const float* __restrict__ bc,
                                             const float* __restrict__ q) {
    __shared__ float red[4];
    int b = blockIdx.y, j = blockIdx.x;
    if (j >= len[b] - 1) return;
    actPair4(b, j, j + 1, j, bc, q, threadIdx.x, red);
}

// ---------------------------------------------------------------------------
// Select for batch b at step stepI; zeroes the merge slot's u for next step's
// atomic split-K accumulation.
// ---------------------------------------------------------------------------
__device__ void doSelect(int b, int stepI, const int* __restrict__ len,
                         float* __restrict__ nodes, float* __restrict__ hf,
                         float* __restrict__ cf,
                         int* sPos, int* sPair, int* sKp) {
    int t = threadIdx.x;
    if (t < 32) sPos[t] = g_slotOf[b * L_ + t];
    if (t < 31) sPair[t] = g_cidx[b * L_ + t];
    __syncthreads();
    int lb = len[b];
    if (stepI < lb - 1) {
        if (t == 0) {
            int cand = lb - 1 - stepI, k = 0;
            float best = -1e30f;
            for (int j = 0; j < cand; j++) {
                float v = g_logit[b * CSLOT + sPair[j]];
                if (v > best) { best = v; k = j; }
            }
            *sKp = k;
        }
        __syncthreads();
        int k = *sKp, cs = sPair[k], mslot = 32 + stepI;
        const float* ch = &g_cacheH[(b * CSLOT + cs) * H_];
        const float* cc = &g_cacheC[(b * CSLOT + cs) * H_];
        float* ph = &g_poolH[(b * PSLOT + mslot) * H_];
        float* pc = &g_poolC[(b * PSLOT + mslot) * H_];
        float* nd = &nodes[(b * 63 + 32 + stepI) * H_];
        for (int j = t; j < H_; j += blockDim.x) {
            float hvv = ch[j], cvv = cc[j];
            ph[j] = hvv; pc[j] = cvv; nd[j] = hvv;
            if (stepI == L_ - 2) { hf[b * H_ + j] = hvv; cf[b * H_ + j] = cvv; }
        }
        {
            float4 z = make_float4(0.f, 0.f, 0.f, 0.f);
            float* zl = g_uL + (b * PSLOT + mslot) * H5_;
            float* zr = g_uR + (b * PSLOT + mslot) * H5_;
            for (int j = t * 4; j < H5_; j += blockDim.x * 4) {
                *(float4*)(zl + j) = z;
                *(float4*)(zr + j) = z;
            }
        }
        if (t < 32) {
            int np = (t < k) ? sPos[t] : (t == k) ? mslot : (t < 31) ? sPos[t + 1] : ZSLOT;
            g_slotOf[b * L_ + t] = np;
        }
        if (t < 31) {
            int np;
            if      (t <  k - 1) np = sPair[t];
            else if (t == k - 1) np = 31 + 2 * stepI;
            else if (t == k)     np = 32 + 2 * stepI;
            else if (t < 30)     np = sPair[t + 1];
            else                 np = DSLOT;
            g_cidx[b * L_ + t] = np;
        }
        if (t == 0) {
            int A = 31 + 2 * stepI, Bc = 32 + 2 * stepI;
            g_tasks[2 * b] = (k > 0) ? make_int4(b, sPos[k - 1], mslot, A)
                                     : make_int4(b, ZSLOT, ZSLOT, DSLOT);
            int r = (k + 2 <= 31) ? sPos[k + 2] : ZSLOT;
            g_tasks[2 * b + 1] = make_int4(b, mslot, r, Bc);
            g_newSlot[b] = mslot;
        }
    } else {
        float* nd = &nodes[(b * 63 + 32 + stepI) * H_];
        if (stepI == L_ - 2) {
            int rs = sPos[0];
            const float* ph = &g_poolH[(b * PSLOT + rs) * H_];
            const float* pc = &g_poolC[(b * PSLOT + rs) * H_];
            for (int j = t; j < H_; j += blockDim.x) {
                float hvv = ph[j];
                nd[j] = hvv; hf[b * H_ + j] = hvv; cf[b * H_ + j] = pc[j];
            }
        } else {
            int cs = sPair[0];
            const float* ch = &g_cacheH[(b * CSLOT + cs) * H_];
            for (int j = t; j < H_; j += blockDim.x) nd[j] = ch[j];
        }
        if (t == 0) {
            g_tasks[2 * b]     = make_int4(b, ZSLOT, ZSLOT, DSLOT);
            g_tasks[2 * b + 1] = make_int4(b, ZSLOT, ZSLOT, DSLOT);
            g_newSlot[b] = ZSLOT;
        }
    }
    __syncthreads();
}

// ---------------------------------------------------------------------------
// Step-0 select only. One CTA per batch.
// ---------------------------------------------------------------------------
__global__ void __launch_bounds__(256) kSel0(const int* __restrict__ len,
                                             float* __restrict__ nodes,
                                             float* __restrict__ hf,
                                             float* __restrict__ cf) {
    __shared__ int sPos[32], sPair[31], sK;
    doSelect(blockIdx.x, 0, len, nodes, hf, cf, sPos, sPair, &sK);
}

// ---------------------------------------------------------------------------
// Fused step kernel: phase1 u-GEMM (grid (80,2), M=32, N=5120, K split 2,
// fp32 atomicAdd = exactly-2-way commutative sum), 160-CTA barrier, phase2
// act (2 tasks, warp halves) + select on CTAs (x<32, y==0).
// ---------------------------------------------------------------------------
__global__ void __launch_bounds__(256) kStep(const int* __restrict__ len,
                                             const float* __restrict__ Wc,
                                             const float* __restrict__ bc,
                                             const float* __restrict__ q,
                                             float* __restrict__ nodes,
                                             float* __restrict__ hf,
                                             float* __restrict__ cf,
                                             int stepI) {
    const int n0g = blockIdx.x * 64;
    const int half = (n0g >= H5_) ? 1 : 0;
    const int nn = n0g - half * H5_;
    const int kb = blockIdx.y * 256;
    __shared__ __align__(16) float As[16][36];
    __shared__ __align__(16) float Ws[16][68];
    __shared__ int sSlot[32];
    __shared__ int sPos[32], sPair[31], sK;
    __shared__ float red[8];
    const int tid = threadIdx.x;
    if (tid < B_) sSlot[tid] = g_newSlot[tid];
    __syncthreads();

    {   // ---- phase 1: u-GEMM
        const int mS = tid >> 2, qS = tid & 3;     // staging (tid<128): rows 0..31
        const int mg = tid >> 4, tx = tid & 15;    // compute: 2 rows, 2 col-pairs
        const float* aPtr = (tid < 128)
            ? g_poolH + (mS * PSLOT + sSlot[mS]) * H_ + kb + qS * 4 : g_poolH;
        const float* bPtr = Wc + (half * H_ + kb + (tid >> 4)) * H5_ + nn + (tid & 15) * 4;
        float4 xr, wv;
        if (tid < 128) xr = *(const float4*)aPtr;
        wv = *(const float4*)bPtr;
        u64 acc[2][2] = {};
        for (int k0 = 0; k0 < 256; k0 += 16) {
            if (tid < 128) {
                As[qS*4+0][mS] = xr.x; As[qS*4+1][mS] = xr.y;
                As[qS*4+2][mS] = xr.z; As[qS*4+3][mS] = xr.w;
            }
            *(float4*)&Ws[tid >> 4][(tid & 15) * 4] = wv;
            __syncthreads();
            if (k0 + 16 < 256) {
                if (tid < 128) xr = *(const float4*)(aPtr + k0 + 16);
                wv = *(const float4*)(bPtr + (k0 + 16) * H5_);
            }
#pragma unroll
            for (int kk = 0; kk < 16; kk++) {
                float a0 = As[kk][mg * 2], a1 = As[kk][mg * 2 + 1];
                u64 b01 = *(const u64*)&Ws[kk][tx*2];
                u64 b23 = *(const u64*)&Ws[kk][32 + tx*2];
                u64 pa0 = pk2(a0, a0), pa1 = pk2(a1, a1);
                FFMA2(acc[0][0], pa0, b01); FFMA2(acc[0][1], pa0, b23);
                FFMA2(acc[1][0], pa1, b01); FFMA2(acc[1][1], pa1, b23);
            }
            __syncthreads();
        }
        float* U = half ? g_uR : g_uL;
#pragma unroll
        for (int e = 0; e < 2; e++) {
            int r = mg * 2 + e;
            float* base = U + (r * PSLOT + sSlot[r]) * H5_ + nn;
            float2 p0 = up2(acc[e][0]), p1 = up2(acc[e][1]);
            atomicAdd(base + tx*2,          p0.x);
            atomicAdd(base + tx*2 + 1,      p0.y);
            atomicAdd(base + 32 + tx*2,     p1.x);
            atomicAdd(base + 32 + tx*2 + 1, p1.y);
        }
    }
    gridBar(stepI - 1);
    // ---- phase 2: act + select (32 CTAs)
    if (blockIdx.y == 0 && blockIdx.x < B_) {
        int b = blockIdx.x;
        int4 tk = (tid < 128) ? g_tasks[2 * b] : g_tasks[2 * b + 1];
        actPair4(b, tk.y, tk.z, tk.w, bc, q, tid & 127, red + ((tid >> 7) << 2));
        __syncthreads();
        doSelect(b, stepI, len, nodes, hf, cf, sPos, sPair, &sK);
    }
}

// ---------------------------------------------------------------------------
extern "C" void kernel_launch(void* const* d_in, const int* in_sizes, int n_in,
                              void* d_out, int out_size) {
    const float* inp = (const float*)d_in[0];
    const int*   len = (const int*)  d_in[1];
    const float* Ww  = (const float*)d_in[2];
    const float* bw  = (const float*)d_in[3];
    const float* Wc  = (const float*)d_in[4];
    const float* bc  = (const float*)d_in[5];
    const float* q   = (const float*)d_in[6];
    float* out   = (float*)d_out;
    float* hf    = out;
    float* cf    = out + B_ * H_;
    float* nodes = out + 2 * B_ * H_;

    kInit<<<16, 256>>>();
    kLeafGemm<<<dim3(16, 8), 128>>>(inp, Ww, bw, nodes);
    kUGemm0<<<dim3(16, 40), 128>>>(Wc);
    kAct0<<<dim3(31, B_), 128>>>(len, bc, q);
    kSel0<<<B_, 256>>>(len, nodes, hf, cf);
    for (int i = 1; i <= L_ - 2; i++)
        kStep<<<dim3(80, 2), 256>>>(len, Wc, bc, q, nodes, hf, cf, i);
}